// round 1
// baseline (speedup 1.0000x reference)
#include <cuda_runtime.h>
#include <math.h>

#define BB 64
#define S1 513
#define SF 512
#define HH 768
#define H4 192           // H/4 float4s per row
#define TSTART 2
#define TSTOP 3

// output offsets (float32 flat tuple)
#define OFF_IPRED 0
#define OFF_CPRED 64
#define OFF_ILOSS 32832
#define OFF_CLOSS 32833
#define OFF_TAGS  32834
#define OFF_ISQA  65602

// scratch (no allocations allowed)
__device__ float4 g_feats[BB * SF];
__device__ float  g_isqa[BB * 2];
__device__ float  g_Z[BB];
__device__ float  g_gold[BB];

// ---------------------------------------------------------------------------
// Kernel A: feats = emb[:,1:] @ crf_W^T + crf_b ;  isqa_logits = emb[:,0] @ fc2_W^T
// warp-per-row, weights staged in SMEM. Memory-bound (~101 MB read).
// ---------------------------------------------------------------------------
__global__ __launch_bounds__(256) void feats_kernel(
    const float* __restrict__ emb, const float* __restrict__ crf_W,
    const float* __restrict__ crf_b, const float* __restrict__ fc2_W)
{
    __shared__ float4 wc[4 * H4];
    __shared__ float4 wf[2 * H4];
    for (int i = threadIdx.x; i < 4 * H4; i += 256) wc[i] = ((const float4*)crf_W)[i];
    for (int i = threadIdx.x; i < 2 * H4; i += 256) wf[i] = ((const float4*)fc2_W)[i];
    __syncthreads();

    int warp = blockIdx.x * 8 + (threadIdx.x >> 5);
    int lane = threadIdx.x & 31;
    if (warp >= BB * S1) return;
    int b = warp / S1;
    int s = warp - b * S1;
    const float4* e4 = (const float4*)emb + (size_t)warp * H4;

    if (s == 0) {
        float a0 = 0.f, a1 = 0.f;
#pragma unroll
        for (int v = 0; v < 6; v++) {
            int k = lane + v * 32;
            float4 e = e4[k];
            float4 w0 = wf[k];
            float4 w1 = wf[H4 + k];
            a0 += e.x * w0.x + e.y * w0.y + e.z * w0.z + e.w * w0.w;
            a1 += e.x * w1.x + e.y * w1.y + e.z * w1.z + e.w * w1.w;
        }
#pragma unroll
        for (int o = 16; o; o >>= 1) {
            a0 += __shfl_xor_sync(0xffffffffu, a0, o);
            a1 += __shfl_xor_sync(0xffffffffu, a1, o);
        }
        if (lane == 0) { g_isqa[b * 2] = a0; g_isqa[b * 2 + 1] = a1; }
    } else {
        float a0 = 0.f, a1 = 0.f, a2 = 0.f, a3 = 0.f;
#pragma unroll
        for (int v = 0; v < 6; v++) {
            int k = lane + v * 32;
            float4 e = e4[k];
            float4 w;
            w = wc[k];          a0 += e.x * w.x + e.y * w.y + e.z * w.z + e.w * w.w;
            w = wc[H4 + k];     a1 += e.x * w.x + e.y * w.y + e.z * w.z + e.w * w.w;
            w = wc[2 * H4 + k]; a2 += e.x * w.x + e.y * w.y + e.z * w.z + e.w * w.w;
            w = wc[3 * H4 + k]; a3 += e.x * w.x + e.y * w.y + e.z * w.z + e.w * w.w;
        }
#pragma unroll
        for (int o = 16; o; o >>= 1) {
            a0 += __shfl_xor_sync(0xffffffffu, a0, o);
            a1 += __shfl_xor_sync(0xffffffffu, a1, o);
            a2 += __shfl_xor_sync(0xffffffffu, a2, o);
            a3 += __shfl_xor_sync(0xffffffffu, a3, o);
        }
        if (lane == 0) {
            float4 o;
            o.x = a0 + __ldg(crf_b + 0);
            o.y = a1 + __ldg(crf_b + 1);
            o.z = a2 + __ldg(crf_b + 2);
            o.w = a3 + __ldg(crf_b + 3);
            g_feats[b * SF + (s - 1)] = o;
        }
    }
}

// ---------------------------------------------------------------------------
// Kernel B: per batch-row CRF. 1 block/row, 4 warps:
//   warp0 lane0: log-partition in exp-domain (renorm by power-of-2 every 8 steps)
//   warp1 lane0: Viterbi forward (packed 2-bit bps) + backtrace, writes crf_pred
//   warp2      : gold score (parallel over t) + writes tags output
// ---------------------------------------------------------------------------
__global__ __launch_bounds__(128) void crf_kernel(
    const int* __restrict__ labels, const float* __restrict__ transitions,
    float* __restrict__ out)
{
    const int b = blockIdx.x;
    __shared__ float4 sfeat[SF];
    __shared__ unsigned bpw[128];
    __shared__ float str[16];
    __shared__ float sEt[16];

    const int tid = threadIdx.x;
    const float4* gf = &g_feats[b * SF];
    for (int i = tid; i < SF; i += 128) sfeat[i] = gf[i];
    if (tid < 16) {
        float tv = transitions[tid];
        str[tid] = tv;
        sEt[tid] = expf(tv);
    }
    __syncthreads();

    const int warp = tid >> 5, lane = tid & 31;

    if (warp == 0 && lane == 0) {
        // ---- log partition Z, exp-domain recurrence ----
        float tr[16], Et[16];
#pragma unroll
        for (int i = 0; i < 16; i++) { tr[i] = str[i]; Et[i] = sEt[i]; }
        float4 f0 = sfeat[0];
        float P0 = __expf(f0.x + tr[8 + 0]);
        float P1 = __expf(f0.y + tr[8 + 1]);
        float P2 = __expf(f0.z + tr[8 + 2]);
        float P3 = __expf(f0.w + tr[8 + 3]);
        float C2 = 0.f;
        for (int t = 1; t < SF; t++) {
            float4 f = sfeat[t];
            float e0 = __expf(f.x), e1 = __expf(f.y), e2 = __expf(f.z), e3 = __expf(f.w);
            float q0 = P0 * Et[0] + P1 * Et[4] + P2 * Et[8]  + P3 * Et[12];
            float q1 = P0 * Et[1] + P1 * Et[5] + P2 * Et[9]  + P3 * Et[13];
            float q2 = P0 * Et[2] + P1 * Et[6] + P2 * Et[10] + P3 * Et[14];
            float q3 = P0 * Et[3] + P1 * Et[7] + P2 * Et[11] + P3 * Et[15];
            P0 = q0 * e0; P1 = q1 * e1; P2 = q2 * e2; P3 = q3 * e3;
            if ((t & 7) == 0) {
                float m = fmaxf(fmaxf(P0, P1), fmaxf(P2, P3));
                int e = (__float_as_int(m) >> 23) - 127;
                C2 += (float)e;
                float sc = __int_as_float((127 - e) << 23); // exact 2^-e
                P0 *= sc; P1 *= sc; P2 *= sc; P3 *= sc;
            }
        }
        float sum = P0 * __expf(tr[3]) + P1 * __expf(tr[7]) +
                    P2 * __expf(tr[11]) + P3 * __expf(tr[15]);
        g_Z[b] = (C2 + __log2f(sum)) * 0.69314718055994530942f;
    }

    if (warp == 1 && lane == 0) {
        // ---- Viterbi forward ----
        float tr[16];
#pragma unroll
        for (int i = 0; i < 16; i++) tr[i] = str[i];
        float4 f0 = sfeat[0];
        float d0 = f0.x + tr[8], d1 = f0.y + tr[9], d2 = f0.z + tr[10], d3 = f0.w + tr[11];
        unsigned wacc = 0;
        for (int t = 1; t < SF; t++) {
            float4 f = sfeat[t];
            float fj[4] = {f.x, f.y, f.z, f.w};
            unsigned byte = 0;
            float nd[4];
#pragma unroll
            for (int j = 0; j < 4; j++) {
                float v0 = d0 + tr[j], v1 = d1 + tr[4 + j];
                float v2 = d2 + tr[8 + j], v3 = d3 + tr[12 + j];
                float m01 = fmaxf(v0, v1); int i01 = (v1 > v0) ? 1 : 0;
                float m23 = fmaxf(v2, v3); int i23 = (v3 > v2) ? 3 : 2;
                int am = (m23 > m01) ? i23 : i01;          // ties -> lowest index
                nd[j] = fmaxf(m01, m23) + fj[j];
                byte |= (unsigned)am << (2 * j);
            }
            d0 = nd[0]; d1 = nd[1]; d2 = nd[2]; d3 = nd[3];
            int s4 = (t - 1) & 3;
            wacc |= byte << (8 * s4);
            if (s4 == 3) { bpw[(t - 1) >> 2] = wacc; wacc = 0; }
        }
        bpw[127] = wacc; // t-1 = 508..510 -> partial last word

        // last tag = argmax(delta + trans[:,STOP]), ties -> lowest index
        float s0 = d0 + tr[3], s1 = d1 + tr[7], s2 = d2 + tr[11], s3 = d3 + tr[15];
        int last = 0; float m = s0;
        if (s1 > m) { m = s1; last = 1; }
        if (s2 > m) { m = s2; last = 2; }
        if (s3 > m) { m = s3; last = 3; }
        float* op = out + OFF_CPRED + b * SF;
        op[SF - 1] = (float)last;
        int tag = last;
        for (int wd = 127; wd >= 0; wd--) {
            unsigned w = bpw[wd];
            int top = (wd == 127) ? 2 : 3;   // valid slots in last word: t-1 = 508..510
            for (int s4 = top; s4 >= 0; s4--) {
                tag = (int)((w >> (8 * s4 + 2 * tag)) & 3u);
                op[wd * 4 + s4] = (float)tag;
            }
        }
    }

    if (warp == 2) {
        // ---- gold score + tags output ----
        float acc = 0.f;
        const int* lb = labels + b * S1;
        for (int t = lane; t < SF; t += 32) {
            int tg = lb[1 + t];
            acc += ((const float*)sfeat)[t * 4 + tg];
            out[OFF_TAGS + b * SF + t] = (float)tg;
            if (t > 0) { int tp = lb[t]; acc += str[tp * 4 + tg]; }
            else       { acc += str[8 + tg]; }                 // START -> tag0
            if (t == SF - 1) acc += str[tg * 4 + 3];           // tag_last -> STOP
        }
#pragma unroll
        for (int o = 16; o; o >>= 1) acc += __shfl_xor_sync(0xffffffffu, acc, o);
        if (lane == 0) g_gold[b] = acc;
    }
}

// ---------------------------------------------------------------------------
// Kernel C: isqa loss/pred, loss means, IsQA copy
// ---------------------------------------------------------------------------
__global__ __launch_bounds__(64) void finalize_kernel(
    const int* __restrict__ IsQA, const float* __restrict__ fc2_b,
    float* __restrict__ out)
{
    __shared__ float sA[BB], sC[BB];
    int b = threadIdx.x;
    float l0 = g_isqa[2 * b] + fc2_b[0];
    float l1 = g_isqa[2 * b + 1] + fc2_b[1];
    int q = IsQA[b];
    float m = fmaxf(l0, l1);
    float lse = m + logf(expf(l0 - m) + expf(l1 - m));
    float chosen = q ? l1 : l0;
    sA[b] = lse - chosen;
    sC[b] = g_Z[b] - g_gold[b];
    out[OFF_IPRED + b] = (l1 > l0) ? 1.f : 0.f;
    out[OFF_ISQA + b] = (float)q;
    __syncthreads();
    if (b == 0) {
        float s1 = 0.f, s2 = 0.f;
        for (int i = 0; i < BB; i++) { s1 += sA[i]; s2 += sC[i]; }
        out[OFF_ILOSS] = s1 * (1.f / BB);
        out[OFF_CLOSS] = s2 * (1.f / BB);
    }
}

extern "C" void kernel_launch(void* const* d_in, const int* in_sizes, int n_in,
                              void* d_out, int out_size)
{
    const float* emb    = (const float*)d_in[0];
    const int*   labels = (const int*)d_in[1];
    const int*   isqa   = (const int*)d_in[2];
    const float* fc2_W  = (const float*)d_in[3];
    const float* fc2_b  = (const float*)d_in[4];
    const float* crf_W  = (const float*)d_in[5];
    const float* crf_b  = (const float*)d_in[6];
    const float* trans  = (const float*)d_in[7];
    float* out = (float*)d_out;

    (void)in_sizes; (void)n_in; (void)out_size;

    feats_kernel<<<(BB * S1 + 7) / 8, 256>>>(emb, crf_W, crf_b, fc2_W);
    crf_kernel<<<BB, 128>>>(labels, trans, out);
    finalize_kernel<<<1, 64>>>(isqa, fc2_b, out);
}

// round 4
// speedup vs baseline: 1.5767x; 1.5767x over previous
#include <cuda_runtime.h>
#include <math.h>

#define BB 64
#define S1 513
#define SF 512
#define HH 768
#define H4 192           // H/4 float4s per row

// output offsets (float32 flat tuple)
#define OFF_IPRED 0
#define OFF_CPRED 64
#define OFF_ILOSS 32832
#define OFF_CLOSS 32833
#define OFF_TAGS  32834
#define OFF_ISQA  65602

// scratch (no allocations allowed)
__device__ float4 g_feats[BB * SF];
__device__ float  g_isqa[BB * 2];
__device__ float  g_Z[BB];
__device__ float  g_gold[BB];

// ---------------------------------------------------------------------------
// Kernel A: feats = emb[:,1:] @ crf_W^T + crf_b
// 4 rows per warp share each SMEM weight load -> L1 wavefronts/row 120 -> 48,
// DRAM becomes the binding resource.
// ---------------------------------------------------------------------------
__global__ __launch_bounds__(256) void feats_kernel(
    const float* __restrict__ emb, const float* __restrict__ crf_W,
    const float* __restrict__ crf_b)
{
    __shared__ float4 wc[4 * H4];
    for (int i = threadIdx.x; i < 4 * H4; i += 256) wc[i] = ((const float4*)crf_W)[i];
    __syncthreads();

    int warp = blockIdx.x * 8 + (threadIdx.x >> 5);
    int lane = threadIdx.x & 31;
    int row0 = warp * 4;                 // rows 0..32767, row = b*512 + s
    int b = row0 >> 9;
    int s0 = row0 & 511;
    const float4* eb = (const float4*)emb + ((size_t)b * S1 + 1 + s0) * H4;

    float a[4][4];
#pragma unroll
    for (int r = 0; r < 4; r++)
#pragma unroll
        for (int j = 0; j < 4; j++) a[r][j] = 0.f;

#pragma unroll
    for (int v = 0; v < 6; v++) {
        int k = lane + v * 32;
        float4 e0 = eb[k];
        float4 e1 = eb[H4 + k];
        float4 e2 = eb[2 * H4 + k];
        float4 e3 = eb[3 * H4 + k];
#pragma unroll
        for (int j = 0; j < 4; j++) {
            float4 w = wc[j * H4 + k];
            a[0][j] += e0.x * w.x + e0.y * w.y + e0.z * w.z + e0.w * w.w;
            a[1][j] += e1.x * w.x + e1.y * w.y + e1.z * w.z + e1.w * w.w;
            a[2][j] += e2.x * w.x + e2.y * w.y + e2.z * w.z + e2.w * w.w;
            a[3][j] += e3.x * w.x + e3.y * w.y + e3.z * w.z + e3.w * w.w;
        }
    }
#pragma unroll
    for (int r = 0; r < 4; r++)
#pragma unroll
        for (int j = 0; j < 4; j++)
#pragma unroll
            for (int o = 16; o; o >>= 1)
                a[r][j] += __shfl_xor_sync(0xffffffffu, a[r][j], o);

    if (lane == 0) {
        float4 cb = __ldg((const float4*)crf_b);
#pragma unroll
        for (int r = 0; r < 4; r++) {
            float4 o;
            o.x = a[r][0] + cb.x; o.y = a[r][1] + cb.y;
            o.z = a[r][2] + cb.z; o.w = a[r][3] + cb.w;
            g_feats[row0 + r] = o;
        }
    }
}

// ---------------------------------------------------------------------------
// Kernel B: per batch-row CRF. 1 block/row, 4 warps:
//   warp0 lane0: log-partition Z (exp-domain, exact-enough)
//   warp1      : Viterbi score chain (exact) storing delta_t to smem
//   warp2      : gold score + tags output
//   warp3      : isqa CLS GEMV (overlapped, free)
// then ALL threads: parallel bp extraction; warp1: parallel integer backtrace.
// ---------------------------------------------------------------------------
__global__ __launch_bounds__(128) void crf_kernel(
    const float* __restrict__ emb, const int* __restrict__ labels,
    const float* __restrict__ transitions, const float* __restrict__ fc2_W,
    float* __restrict__ out)
{
    const int b = blockIdx.x;
    __shared__ float4 sfeat[SF];        // 8 KB
    __shared__ float4 sdelta[SF];       // 8 KB
    __shared__ unsigned char sbp[SF];   // bp byte per t (t=1..511)
    __shared__ float str[16];
    __shared__ float sEt[16];

    const int tid = threadIdx.x;
    const float4* gf = &g_feats[b * SF];
    for (int i = tid; i < SF; i += 128) sfeat[i] = gf[i];
    if (tid < 16) {
        float tv = transitions[tid];
        str[tid] = tv;
        sEt[tid] = expf(tv);
    }
    __syncthreads();

    const int warp = tid >> 5, lane = tid & 31;

    if (warp == 0 && lane == 0) {
        // ---- log partition Z, exp-domain recurrence (exact enough) ----
        float tr[16], Et[16];
#pragma unroll
        for (int i = 0; i < 16; i++) { tr[i] = str[i]; Et[i] = sEt[i]; }
        float4 f0 = sfeat[0];
        float P0 = __expf(f0.x + tr[8 + 0]);
        float P1 = __expf(f0.y + tr[8 + 1]);
        float P2 = __expf(f0.z + tr[8 + 2]);
        float P3 = __expf(f0.w + tr[8 + 3]);
        float C2 = 0.f;
        for (int t = 1; t < SF; t++) {
            float4 f = sfeat[t];
            float e0 = __expf(f.x), e1 = __expf(f.y), e2 = __expf(f.z), e3 = __expf(f.w);
            float q0 = P0 * Et[0] + P1 * Et[4] + P2 * Et[8]  + P3 * Et[12];
            float q1 = P0 * Et[1] + P1 * Et[5] + P2 * Et[9]  + P3 * Et[13];
            float q2 = P0 * Et[2] + P1 * Et[6] + P2 * Et[10] + P3 * Et[14];
            float q3 = P0 * Et[3] + P1 * Et[7] + P2 * Et[11] + P3 * Et[15];
            P0 = q0 * e0; P1 = q1 * e1; P2 = q2 * e2; P3 = q3 * e3;
            if ((t & 7) == 0) {
                float m = fmaxf(fmaxf(P0, P1), fmaxf(P2, P3));
                int e = (__float_as_int(m) >> 23) - 127;
                C2 += (float)e;
                float sc = __int_as_float((127 - e) << 23); // exact 2^-e
                P0 *= sc; P1 *= sc; P2 *= sc; P3 *= sc;
            }
        }
        float sum = P0 * __expf(tr[3]) + P1 * __expf(tr[7]) +
                    P2 * __expf(tr[11]) + P3 * __expf(tr[15]);
        g_Z[b] = (C2 + __log2f(sum)) * 0.69314718055994530942f;
    }

    if (warp == 1) {
        // ---- Viterbi score chain only (no argmax), store deltas ----
        float tr[16];
#pragma unroll
        for (int i = 0; i < 16; i++) tr[i] = str[i];
        float4 f0 = sfeat[0];
        float d0 = f0.x + tr[8], d1 = f0.y + tr[9], d2 = f0.z + tr[10], d3 = f0.w + tr[11];
        if (lane == 0) sdelta[0] = make_float4(d0, d1, d2, d3);
#pragma unroll 4
        for (int t = 1; t < SF; t++) {
            float4 f = sfeat[t];
            float n0 = fmaxf(fmaxf(d0 + tr[0],  d1 + tr[4]),  fmaxf(d2 + tr[8],  d3 + tr[12])) + f.x;
            float n1 = fmaxf(fmaxf(d0 + tr[1],  d1 + tr[5]),  fmaxf(d2 + tr[9],  d3 + tr[13])) + f.y;
            float n2 = fmaxf(fmaxf(d0 + tr[2],  d1 + tr[6]),  fmaxf(d2 + tr[10], d3 + tr[14])) + f.z;
            float n3 = fmaxf(fmaxf(d0 + tr[3],  d1 + tr[7]),  fmaxf(d2 + tr[11], d3 + tr[15])) + f.w;
            d0 = n0; d1 = n1; d2 = n2; d3 = n3;
            if (lane == 0) sdelta[t] = make_float4(d0, d1, d2, d3);
        }
    }

    if (warp == 2) {
        // ---- gold score + tags output ----
        float acc = 0.f;
        const int* lb = labels + b * S1;
        for (int t = lane; t < SF; t += 32) {
            int tg = lb[1 + t];
            acc += ((const float*)sfeat)[t * 4 + tg];
            out[OFF_TAGS + b * SF + t] = (float)tg;
            if (t > 0) { int tp = lb[t]; acc += str[tp * 4 + tg]; }
            else       { acc += str[8 + tg]; }                 // START -> tag0
            if (t == SF - 1) acc += str[tg * 4 + 3];           // tag_last -> STOP
        }
#pragma unroll
        for (int o = 16; o; o >>= 1) acc += __shfl_xor_sync(0xffffffffu, acc, o);
        if (lane == 0) g_gold[b] = acc;
    }

    if (warp == 3) {
        // ---- isqa logits for this row's CLS token (overlapped, free) ----
        const float4* e4 = (const float4*)emb + (size_t)b * S1 * H4;
        const float4* w4 = (const float4*)fc2_W;
        float a0 = 0.f, a1 = 0.f;
#pragma unroll
        for (int v = 0; v < 6; v++) {
            int k = lane + v * 32;
            float4 e = e4[k];
            float4 w0 = __ldg(w4 + k);
            float4 w1 = __ldg(w4 + H4 + k);
            a0 += e.x * w0.x + e.y * w0.y + e.z * w0.z + e.w * w0.w;
            a1 += e.x * w1.x + e.y * w1.y + e.z * w1.z + e.w * w1.w;
        }
#pragma unroll
        for (int o = 16; o; o >>= 1) {
            a0 += __shfl_xor_sync(0xffffffffu, a0, o);
            a1 += __shfl_xor_sync(0xffffffffu, a1, o);
        }
        if (lane == 0) { g_isqa[b * 2] = a0; g_isqa[b * 2 + 1] = a1; }
    }

    __syncthreads();

    // ---- parallel backpointer extraction (exact: same arithmetic/assoc as ref) ----
    {
        float trl[16];
#pragma unroll
        for (int i = 0; i < 16; i++) trl[i] = str[i];
#pragma unroll
        for (int p = 0; p < 4; p++) {
            int t = 1 + tid + p * 128;
            if (t < SF) {
                float4 d = sdelta[t - 1];
                unsigned byte = 0;
#pragma unroll
                for (int j = 0; j < 4; j++) {
                    float v0 = d.x + trl[j],     v1 = d.y + trl[4 + j];
                    float v2 = d.z + trl[8 + j], v3 = d.w + trl[12 + j];
                    float m01 = fmaxf(v0, v1); int i01 = (v1 > v0) ? 1 : 0;
                    float m23 = fmaxf(v2, v3); int i23 = (v3 > v2) ? 3 : 2;
                    int am = (m23 > m01) ? i23 : i01;   // ties -> lowest index
                    byte |= (unsigned)am << (2 * j);
                }
                sbp[t] = (unsigned char)byte;
            }
        }
    }
    __syncthreads();

    if (warp == 1) {
        // ---- parallel integer backtrace via tag-map composition ----
        float4 dl = sdelta[SF - 1];
        float s0 = dl.x + str[3], s1 = dl.y + str[7], s2 = dl.z + str[11], s3 = dl.w + str[15];
        int last = 0; float m = s0;
        if (s1 > m) { m = s1; last = 1; }
        if (s2 > m) { m = s2; last = 2; }
        if (s3 > m) { m = s3; last = 3; }

        const int c = lane;
        const int a0i = 16 * c + 1;
        unsigned char bb[16];
        unsigned F = 0xE4u;                 // identity map: 11 10 01 00
#pragma unroll
        for (int k = 15; k >= 0; k--) {
            int t = a0i + k;
            if (t < SF) {
                unsigned mp = sbp[t];
                bb[k] = (unsigned char)mp;
                unsigned nf = 0;
#pragma unroll
                for (int e = 0; e < 4; e++) {
                    unsigned fe = (F >> (2 * e)) & 3u;
                    nf |= ((mp >> (2 * fe)) & 3u) << (2 * e);
                }
                F = nf;
            }
        }
        // suffix scan: S_c = F_c o F_{c+1} o ... o F_31
        unsigned S = F;
#pragma unroll
        for (int s = 1; s < 32; s <<= 1) {
            unsigned o = __shfl_down_sync(0xffffffffu, S, s);
            if (c + s < 32) {
                unsigned ns = 0;
#pragma unroll
                for (int e = 0; e < 4; e++) {
                    unsigned be = (o >> (2 * e)) & 3u;
                    ns |= ((S >> (2 * be)) & 3u) << (2 * e);
                }
                S = ns;
            }
        }
        unsigned Snext = __shfl_down_sync(0xffffffffu, S, 1);
        int exitc = (c == 31) ? last : (int)((Snext >> (2 * last)) & 3u);

        unsigned pw = (c == 31) ? ((unsigned)last << 30) : 0u;
        int tag = exitc;
#pragma unroll
        for (int k = 15; k >= 0; k--) {
            int t = a0i + k;
            if (t < SF) {
                tag = (bb[k] >> (2 * tag)) & 3;
                pw |= (unsigned)tag << (2 * k);
            }
        }
        float* op = out + OFF_CPRED + b * SF + 16 * c;
#pragma unroll
        for (int q = 0; q < 4; q++) {
            float4 w4;
            w4.x = (float)((pw >> (8 * q)) & 3u);
            w4.y = (float)((pw >> (8 * q + 2)) & 3u);
            w4.z = (float)((pw >> (8 * q + 4)) & 3u);
            w4.w = (float)((pw >> (8 * q + 6)) & 3u);
            ((float4*)op)[q] = w4;
        }
    }
}

// ---------------------------------------------------------------------------
// Kernel C: isqa loss/pred, loss means, IsQA copy
// ---------------------------------------------------------------------------
__global__ __launch_bounds__(64) void finalize_kernel(
    const int* __restrict__ IsQA, const float* __restrict__ fc2_b,
    float* __restrict__ out)
{
    __shared__ float sA[BB], sC[BB];
    int b = threadIdx.x;
    float l0 = g_isqa[2 * b] + fc2_b[0];
    float l1 = g_isqa[2 * b + 1] + fc2_b[1];
    int q = IsQA[b];
    float m = fmaxf(l0, l1);
    float lse = m + logf(expf(l0 - m) + expf(l1 - m));
    float chosen = q ? l1 : l0;
    sA[b] = lse - chosen;
    sC[b] = g_Z[b] - g_gold[b];
    out[OFF_IPRED + b] = (l1 > l0) ? 1.f : 0.f;
    out[OFF_ISQA + b] = (float)q;
    __syncthreads();
    if (b == 0) {
        float s1 = 0.f, s2 = 0.f;
        for (int i = 0; i < BB; i++) { s1 += sA[i]; s2 += sC[i]; }
        out[OFF_ILOSS] = s1 * (1.f / BB);
        out[OFF_CLOSS] = s2 * (1.f / BB);
    }
}

extern "C" void kernel_launch(void* const* d_in, const int* in_sizes, int n_in,
                              void* d_out, int out_size)
{
    const float* emb    = (const float*)d_in[0];
    const int*   labels = (const int*)d_in[1];
    const int*   isqa   = (const int*)d_in[2];
    const float* fc2_W  = (const float*)d_in[3];
    const float* fc2_b  = (const float*)d_in[4];
    const float* crf_W  = (const float*)d_in[5];
    const float* crf_b  = (const float*)d_in[6];
    const float* trans  = (const float*)d_in[7];
    float* out = (float*)d_out;

    (void)in_sizes; (void)n_in; (void)out_size;

    feats_kernel<<<1024, 256>>>(emb, crf_W, crf_b);
    crf_kernel<<<BB, 128>>>(emb, labels, trans, fc2_W, out);
    finalize_kernel<<<1, 64>>>(isqa, fc2_b, out);
}

// round 5
// speedup vs baseline: 1.8910x; 1.1994x over previous
#include <cuda_runtime.h>
#include <math.h>

#define BB 64
#define S1 513
#define SF 512
#define HH 768
#define H4 192           // H/4 float4s per row

// output offsets (float32 flat tuple)
#define OFF_IPRED 0
#define OFF_CPRED 64
#define OFF_ILOSS 32832
#define OFF_CLOSS 32833
#define OFF_TAGS  32834
#define OFF_ISQA  65602

typedef unsigned long long u64;

__device__ __forceinline__ u64 pk2(float lo, float hi) {
    u64 r; asm("mov.b64 %0,{%1,%2};" : "=l"(r) : "f"(lo), "f"(hi)); return r;
}
__device__ __forceinline__ void upk2(u64 v, float& lo, float& hi) {
    asm("mov.b64 {%0,%1}, %2;" : "=f"(lo), "=f"(hi) : "l"(v));
}
__device__ __forceinline__ u64 ffma2(u64 a, u64 b, u64 c) {
    u64 d; asm("fma.rn.f32x2 %0,%1,%2,%3;" : "=l"(d) : "l"(a), "l"(b), "l"(c)); return d;
}
__device__ __forceinline__ u64 fmul2(u64 a, u64 b) {
    u64 d; asm("mul.rn.f32x2 %0,%1,%2;" : "=l"(d) : "l"(a), "l"(b)); return d;
}
__device__ __forceinline__ u64 fadd2(u64 a, u64 b) {
    u64 d; asm("add.rn.f32x2 %0,%1,%2;" : "=l"(d) : "l"(a), "l"(b)); return d;
}

// scratch (no allocations allowed)
__device__ float4 g_feats[BB * SF];
__device__ float  g_isqa[BB * 2];
__device__ float  g_Z[BB];
__device__ float  g_gold[BB];

// ---------------------------------------------------------------------------
// Kernel A: feats = emb[:,1:] @ crf_W^T + crf_b
// 2 rows/warp: regs ~48 -> 5 blocks/SM (occupancy ~60%) to cover DRAM latency.
// ---------------------------------------------------------------------------
__global__ __launch_bounds__(256) void feats_kernel(
    const float* __restrict__ emb, const float* __restrict__ crf_W,
    const float* __restrict__ crf_b)
{
    __shared__ float4 wc[4 * H4];
    for (int i = threadIdx.x; i < 4 * H4; i += 256) wc[i] = ((const float4*)crf_W)[i];
    __syncthreads();

    int warp = blockIdx.x * 8 + (threadIdx.x >> 5);
    int lane = threadIdx.x & 31;
    int row0 = warp * 2;                 // rows 0..32767, row = b*512 + s
    int b = row0 >> 9;
    int s0 = row0 & 511;
    const float4* eb = (const float4*)emb + ((size_t)b * S1 + 1 + s0) * H4;

    float a[2][4];
#pragma unroll
    for (int r = 0; r < 2; r++)
#pragma unroll
        for (int j = 0; j < 4; j++) a[r][j] = 0.f;

#pragma unroll
    for (int v = 0; v < 6; v++) {
        int k = lane + v * 32;
        float4 e0 = eb[k];
        float4 e1 = eb[H4 + k];
#pragma unroll
        for (int j = 0; j < 4; j++) {
            float4 w = wc[j * H4 + k];
            a[0][j] += e0.x * w.x + e0.y * w.y + e0.z * w.z + e0.w * w.w;
            a[1][j] += e1.x * w.x + e1.y * w.y + e1.z * w.z + e1.w * w.w;
        }
    }
#pragma unroll
    for (int r = 0; r < 2; r++)
#pragma unroll
        for (int j = 0; j < 4; j++)
#pragma unroll
            for (int o = 16; o; o >>= 1)
                a[r][j] += __shfl_xor_sync(0xffffffffu, a[r][j], o);

    if (lane == 0) {
        float4 cb = __ldg((const float4*)crf_b);
#pragma unroll
        for (int r = 0; r < 2; r++) {
            float4 o;
            o.x = a[r][0] + cb.x; o.y = a[r][1] + cb.y;
            o.z = a[r][2] + cb.z; o.w = a[r][3] + cb.w;
            g_feats[row0 + r] = o;
        }
    }
}

// ---------------------------------------------------------------------------
// Kernel B: per batch-row CRF. 1 block/row, 4 warps:
//   warp0 lane0: log-partition Z via packed f32x2 chain over prefolded G mats
//   warp1 lane0: Viterbi chain (bit-exact, packed ADD2 + scalar FMNMX)
//   warp2      : gold score + tags output
//   warp3      : isqa CLS GEMV (overlapped)
// then all: parallel bp extraction; warp1: parallel integer backtrace.
// ---------------------------------------------------------------------------
__global__ __launch_bounds__(128) void crf_kernel(
    const float* __restrict__ emb, const int* __restrict__ labels,
    const float* __restrict__ transitions, const float* __restrict__ fc2_W,
    float* __restrict__ out)
{
    const int b = blockIdx.x;
    __shared__ ulonglong2 sGA[SF];      // 8KB: ((G00,G01),(G10,G11))
    __shared__ ulonglong2 sGB[SF];      // 8KB: ((G20,G21),(G30,G31))
    __shared__ ulonglong2 sGC[SF];      // 8KB: cols 2,3 rows 0,1
    __shared__ ulonglong2 sGD[SF];      // 8KB: cols 2,3 rows 2,3
    __shared__ float4 sdelta[SF];       // 8KB
    __shared__ unsigned char sbp[SF];
    __shared__ float str[16];
    __shared__ float sEt[16];

    const int tid = threadIdx.x;
    const float4* gf = &g_feats[b * SF];

    if (tid < 16) {
        float tv = transitions[tid];
        str[tid] = tv;
        sEt[tid] = expf(tv);
    }
    __syncthreads();

    // ---- parallel G precompute: G[i][j] = exp(tr[i][j]) * exp(f_t[j]) ----
    {
        float Et[16];
#pragma unroll
        for (int i = 0; i < 16; i++) Et[i] = sEt[i];
        for (int t = tid; t < SF; t += 128) {
            float4 f = gf[t];
            float e0 = __expf(f.x), e1 = __expf(f.y), e2 = __expf(f.z), e3 = __expf(f.w);
            *((float4*)(sGA + t)) = make_float4(Et[0]*e0,  Et[1]*e1,  Et[4]*e0,  Et[5]*e1);
            *((float4*)(sGB + t)) = make_float4(Et[8]*e0,  Et[9]*e1,  Et[12]*e0, Et[13]*e1);
            *((float4*)(sGC + t)) = make_float4(Et[2]*e2,  Et[3]*e3,  Et[6]*e2,  Et[7]*e3);
            *((float4*)(sGD + t)) = make_float4(Et[10]*e2, Et[11]*e3, Et[14]*e2, Et[15]*e3);
        }
    }
    __syncthreads();

    const int warp = tid >> 5, lane = tid & 31;

    if (warp == 0 && lane == 0) {
        // ---- Z chain: P' = G^T P, packed f32x2, renorm by 2^-e every 8 ----
        float4 f0 = gf[0];
        float p0 = __expf(f0.x + str[8]);
        float p1 = __expf(f0.y + str[9]);
        float p2 = __expf(f0.z + str[10]);
        float p3 = __expf(f0.w + str[11]);
        u64 pp0 = pk2(p0, p0), pp1 = pk2(p1, p1), pp2 = pk2(p2, p2), pp3 = pk2(p3, p3);
        float C2 = 0.f;
        int t = 1;

#define ZSTEP(tt)  {                                              \
        ulonglong2 A = sGA[tt], B = sGB[tt], C = sGC[tt], D = sGD[tt]; \
        u64 q01 = ffma2(pp1, A.y, fmul2(pp0, A.x));               \
        q01 = ffma2(pp2, B.x, q01); q01 = ffma2(pp3, B.y, q01);   \
        u64 q23 = ffma2(pp1, C.y, fmul2(pp0, C.x));               \
        q23 = ffma2(pp2, D.x, q23); q23 = ffma2(pp3, D.y, q23);   \
        upk2(q01, p0, p1); upk2(q23, p2, p3); }

        for (int g = 0; g < 63; g++) {
#pragma unroll
            for (int u = 0; u < 8; u++) {
                ZSTEP(t);
                if (u < 7) { pp0 = pk2(p0,p0); pp1 = pk2(p1,p1); pp2 = pk2(p2,p2); pp3 = pk2(p3,p3); }
                t++;
            }
            // renorm (exact power-of-2)
            float m = fmaxf(fmaxf(p0, p1), fmaxf(p2, p3));
            int e = (__float_as_int(m) >> 23) - 127;
            C2 += (float)e;
            float sc = __int_as_float((127 - e) << 23);
            p0 *= sc; p1 *= sc; p2 *= sc; p3 *= sc;
            pp0 = pk2(p0,p0); pp1 = pk2(p1,p1); pp2 = pk2(p2,p2); pp3 = pk2(p3,p3);
        }
#pragma unroll
        for (int u = 0; u < 7; u++) {
            ZSTEP(t);
            pp0 = pk2(p0,p0); pp1 = pk2(p1,p1); pp2 = pk2(p2,p2); pp3 = pk2(p3,p3);
            t++;
        }
        float sum = p0 * sEt[3] + p1 * sEt[7] + p2 * sEt[11] + p3 * sEt[15];
        g_Z[b] = (C2 + __log2f(sum)) * 0.69314718055994530942f;
#undef ZSTEP
    }

    if (warp == 1 && lane == 0) {
        // ---- Viterbi chain: bit-exact (ADD2 componentwise == scalar FADD) ----
        float tr[16];
#pragma unroll
        for (int i = 0; i < 16; i++) tr[i] = str[i];
        u64 TA0 = pk2(tr[0], tr[4]),  TA1 = pk2(tr[1], tr[5]);
        u64 TA2 = pk2(tr[2], tr[6]),  TA3 = pk2(tr[3], tr[7]);
        u64 TB0 = pk2(tr[8], tr[12]), TB1 = pk2(tr[9], tr[13]);
        u64 TB2 = pk2(tr[10], tr[14]), TB3 = pk2(tr[11], tr[15]);

        float4 f0 = gf[0];
        float d0 = f0.x + tr[8], d1 = f0.y + tr[9], d2 = f0.z + tr[10], d3 = f0.w + tr[11];
        sdelta[0] = make_float4(d0, d1, d2, d3);
        u64 D01 = pk2(d0, d1), D23 = pk2(d2, d3);

#define VSTEP(fv, tt) {                                            \
        u64 a0 = fadd2(D01, TA0), a1 = fadd2(D01, TA1);            \
        u64 a2 = fadd2(D01, TA2), a3 = fadd2(D01, TA3);            \
        u64 b0 = fadd2(D23, TB0), b1 = fadd2(D23, TB1);            \
        u64 b2 = fadd2(D23, TB2), b3 = fadd2(D23, TB3);            \
        float x0,x1,y0,y1,x2,x3,y2,y3,x4,x5,y4,y5,x6,x7,y6,y7;     \
        upk2(a0,x0,x1); upk2(b0,y0,y1);                            \
        upk2(a1,x2,x3); upk2(b1,y2,y3);                            \
        upk2(a2,x4,x5); upk2(b2,y4,y5);                            \
        upk2(a3,x6,x7); upk2(b3,y6,y7);                            \
        float n0 = fmaxf(fmaxf(x0,x1), fmaxf(y0,y1)) + (fv).x;     \
        float n1 = fmaxf(fmaxf(x2,x3), fmaxf(y2,y3)) + (fv).y;     \
        float n2 = fmaxf(fmaxf(x4,x5), fmaxf(y4,y5)) + (fv).z;     \
        float n3 = fmaxf(fmaxf(x6,x7), fmaxf(y6,y7)) + (fv).w;     \
        D01 = pk2(n0, n1); D23 = pk2(n2, n3);                      \
        sdelta[tt] = make_float4(n0, n1, n2, n3); }

        float4 nb[8];
#pragma unroll
        for (int u = 0; u < 8; u++) nb[u] = gf[1 + u];
        int t0 = 1;
        for (int g = 0; g < 63; g++) {
            float4 cu[8];
#pragma unroll
            for (int u = 0; u < 8; u++) cu[u] = nb[u];
#pragma unroll
            for (int u = 0; u < 8; u++) {
                int idx = t0 + 8 + u;
                nb[u] = gf[idx < SF ? idx : SF - 1];
            }
#pragma unroll
            for (int u = 0; u < 8; u++) VSTEP(cu[u], t0 + u);
            t0 += 8;
        }
#pragma unroll
        for (int u = 0; u < 7; u++) VSTEP(nb[u], 505 + u);
#undef VSTEP
    }

    if (warp == 2) {
        // ---- gold score + tags output (feats from global) ----
        float acc = 0.f;
        const int* lb = labels + b * S1;
        const float* gff = (const float*)gf;
        for (int t = lane; t < SF; t += 32) {
            int tg = lb[1 + t];
            acc += gff[t * 4 + tg];
            out[OFF_TAGS + b * SF + t] = (float)tg;
            if (t > 0) { int tp = lb[t]; acc += str[tp * 4 + tg]; }
            else       { acc += str[8 + tg]; }                 // START -> tag0
            if (t == SF - 1) acc += str[tg * 4 + 3];           // tag_last -> STOP
        }
#pragma unroll
        for (int o = 16; o; o >>= 1) acc += __shfl_xor_sync(0xffffffffu, acc, o);
        if (lane == 0) g_gold[b] = acc;
    }

    if (warp == 3) {
        // ---- isqa logits for this row's CLS token (overlapped) ----
        const float4* e4 = (const float4*)emb + (size_t)b * S1 * H4;
        const float4* w4 = (const float4*)fc2_W;
        float a0 = 0.f, a1 = 0.f;
#pragma unroll
        for (int v = 0; v < 6; v++) {
            int k = lane + v * 32;
            float4 e = e4[k];
            float4 w0 = __ldg(w4 + k);
            float4 w1 = __ldg(w4 + H4 + k);
            a0 += e.x * w0.x + e.y * w0.y + e.z * w0.z + e.w * w0.w;
            a1 += e.x * w1.x + e.y * w1.y + e.z * w1.z + e.w * w1.w;
        }
#pragma unroll
        for (int o = 16; o; o >>= 1) {
            a0 += __shfl_xor_sync(0xffffffffu, a0, o);
            a1 += __shfl_xor_sync(0xffffffffu, a1, o);
        }
        if (lane == 0) { g_isqa[b * 2] = a0; g_isqa[b * 2 + 1] = a1; }
    }

    __syncthreads();

    // ---- parallel backpointer extraction (exact: same arithmetic as ref) ----
    {
        float trl[16];
#pragma unroll
        for (int i = 0; i < 16; i++) trl[i] = str[i];
#pragma unroll
        for (int p = 0; p < 4; p++) {
            int t = 1 + tid + p * 128;
            if (t < SF) {
                float4 d = sdelta[t - 1];
                unsigned byte = 0;
#pragma unroll
                for (int j = 0; j < 4; j++) {
                    float v0 = d.x + trl[j],     v1 = d.y + trl[4 + j];
                    float v2 = d.z + trl[8 + j], v3 = d.w + trl[12 + j];
                    float m01 = fmaxf(v0, v1); int i01 = (v1 > v0) ? 1 : 0;
                    float m23 = fmaxf(v2, v3); int i23 = (v3 > v2) ? 3 : 2;
                    int am = (m23 > m01) ? i23 : i01;   // ties -> lowest index
                    byte |= (unsigned)am << (2 * j);
                }
                sbp[t] = (unsigned char)byte;
            }
        }
    }
    __syncthreads();

    if (warp == 1) {
        // ---- parallel integer backtrace via tag-map composition ----
        float4 dl = sdelta[SF - 1];
        float s0 = dl.x + str[3], s1 = dl.y + str[7], s2 = dl.z + str[11], s3 = dl.w + str[15];
        int last = 0; float m = s0;
        if (s1 > m) { m = s1; last = 1; }
        if (s2 > m) { m = s2; last = 2; }
        if (s3 > m) { m = s3; last = 3; }

        const int c = lane;
        const int a0i = 16 * c + 1;
        unsigned char bb[16];
        unsigned F = 0xE4u;                 // identity map: 11 10 01 00
#pragma unroll
        for (int k = 15; k >= 0; k--) {
            int t = a0i + k;
            if (t < SF) {
                unsigned mp = sbp[t];
                bb[k] = (unsigned char)mp;
                unsigned nf = 0;
#pragma unroll
                for (int e = 0; e < 4; e++) {
                    unsigned fe = (F >> (2 * e)) & 3u;
                    nf |= ((mp >> (2 * fe)) & 3u) << (2 * e);
                }
                F = nf;
            }
        }
        // suffix scan: S_c = F_c o F_{c+1} o ... o F_31
        unsigned S = F;
#pragma unroll
        for (int s = 1; s < 32; s <<= 1) {
            unsigned o = __shfl_down_sync(0xffffffffu, S, s);
            if (c + s < 32) {
                unsigned ns = 0;
#pragma unroll
                for (int e = 0; e < 4; e++) {
                    unsigned be = (o >> (2 * e)) & 3u;
                    ns |= ((S >> (2 * be)) & 3u) << (2 * e);
                }
                S = ns;
            }
        }
        unsigned Snext = __shfl_down_sync(0xffffffffu, S, 1);
        int exitc = (c == 31) ? last : (int)((Snext >> (2 * last)) & 3u);

        unsigned pw = (c == 31) ? ((unsigned)last << 30) : 0u;
        int tag = exitc;
#pragma unroll
        for (int k = 15; k >= 0; k--) {
            int t = a0i + k;
            if (t < SF) {
                tag = (bb[k] >> (2 * tag)) & 3;
                pw |= (unsigned)tag << (2 * k);
            }
        }
        float* op = out + OFF_CPRED + b * SF + 16 * c;
#pragma unroll
        for (int q = 0; q < 4; q++) {
            float4 w4;
            w4.x = (float)((pw >> (8 * q)) & 3u);
            w4.y = (float)((pw >> (8 * q + 2)) & 3u);
            w4.z = (float)((pw >> (8 * q + 4)) & 3u);
            w4.w = (float)((pw >> (8 * q + 6)) & 3u);
            ((float4*)op)[q] = w4;
        }
    }
}

// ---------------------------------------------------------------------------
// Kernel C: isqa loss/pred, loss means, IsQA copy
// ---------------------------------------------------------------------------
__global__ __launch_bounds__(64) void finalize_kernel(
    const int* __restrict__ IsQA, const float* __restrict__ fc2_b,
    float* __restrict__ out)
{
    __shared__ float sA[BB], sC[BB];
    int b = threadIdx.x;
    float l0 = g_isqa[2 * b] + fc2_b[0];
    float l1 = g_isqa[2 * b + 1] + fc2_b[1];
    int q = IsQA[b];
    float m = fmaxf(l0, l1);
    float lse = m + logf(expf(l0 - m) + expf(l1 - m));
    float chosen = q ? l1 : l0;
    sA[b] = lse - chosen;
    sC[b] = g_Z[b] - g_gold[b];
    out[OFF_IPRED + b] = (l1 > l0) ? 1.f : 0.f;
    out[OFF_ISQA + b] = (float)q;
    __syncthreads();
    if (b == 0) {
        float s1 = 0.f, s2 = 0.f;
        for (int i = 0; i < BB; i++) { s1 += sA[i]; s2 += sC[i]; }
        out[OFF_ILOSS] = s1 * (1.f / BB);
        out[OFF_CLOSS] = s2 * (1.f / BB);
    }
}

extern "C" void kernel_launch(void* const* d_in, const int* in_sizes, int n_in,
                              void* d_out, int out_size)
{
    const float* emb    = (const float*)d_in[0];
    const int*   labels = (const int*)d_in[1];
    const int*   isqa   = (const int*)d_in[2];
    const float* fc2_W  = (const float*)d_in[3];
    const float* fc2_b  = (const float*)d_in[4];
    const float* crf_W  = (const float*)d_in[5];
    const float* crf_b  = (const float*)d_in[6];
    const float* trans  = (const float*)d_in[7];
    float* out = (float*)d_out;

    (void)in_sizes; (void)n_in; (void)out_size;

    feats_kernel<<<2048, 256>>>(emb, crf_W, crf_b);
    crf_kernel<<<BB, 128>>>(emb, labels, trans, fc2_W, out);
    finalize_kernel<<<1, 64>>>(isqa, fc2_b, out);
}